// round 9
// baseline (speedup 1.0000x reference)
#include <cuda_runtime.h>
#include <cstdint>

#define S_ 128
#define B_ 32
#define H_ 512
#define V_ 10000
#define L_ 2

// ---------------- device scratch (no allocations allowed) ----------------
__device__ float g_ax0[S_ * B_ * 3 * H_];          // precomputed layer-0 input projections [s][b][g][h]
__device__ float g_tops[S_ * B_ * H_];             // top-layer outputs per step
__device__ float g_h[2 * B_ * H_];                 // running hidden states [layer][b][h]
__device__ float g_rh0[B_ * H_];                   // r0 * h0
__device__ float g_z0[B_ * H_];
__device__ float g_dr1[B_ * H_];                   // raw h1@U1[0]
__device__ float g_dz1[B_ * H_];                   // raw h1@U1[1]
__device__ float g_rh1[B_ * H_];
__device__ float g_z1v[B_ * H_];
__device__ float g_axh1[B_ * H_];
__device__ unsigned g_barcnt = 0;
__device__ unsigned g_bargen = 0;

// ---------------- grid barrier (all blocks resident: grid == #SMs) --------
__device__ __forceinline__ void grid_barrier(int nblocks) {
    __syncthreads();
    if (threadIdx.x == 0) {
        __threadfence();  // release my writes (fence.gpu -> CCTL.IVALL)
        volatile unsigned* vgen = &g_bargen;
        unsigned gen = *vgen;
        unsigned arrived = atomicAdd(&g_barcnt, 1u);
        if (arrived == (unsigned)(nblocks - 1)) {
            atomicExch(&g_barcnt, 0u);
            __threadfence();
            atomicAdd(&g_bargen, 1u);
        } else {
            while (*vgen == gen) { __nanosleep(64); }
        }
        __threadfence();  // acquire: invalidate stale L1 lines
    }
    __syncthreads();
}

__device__ __forceinline__ float sigmoidf_(float x) {
    return 1.0f / (1.0f + expf(-x));
}

// ---------------- Kernel 1: X0 = emb[tokens] @ Wx0[g] + bx0[g] ------------
// A gathered [4096,512], B = Wx[0][g] is [K=512][N=512] (n contiguous).
// grid: (N/128=4, M/128=32, 3 gates), 256 threads, 128x128 tile, BK=16.
__global__ __launch_bounds__(256) void x0_gemm(const int* __restrict__ tok32,
                                               const float* __restrict__ emb,
                                               const float* __restrict__ Wx,
                                               const float* __restrict__ bx) {
    const int g = blockIdx.z;
    const float* Bg = Wx + (size_t)g * H_ * H_;   // layer 0, gate g
    const float* bg = bx + g * H_;

    __shared__ float As[16][132];
    __shared__ float Bs[16][132];

    const int tid = threadIdx.x;
    const int bm = blockIdx.y * 128;
    const int bn = blockIdx.x * 128;

    // detect token dtype: int64 little-endian => odd int32 lanes are all zero
    int or_odd = 0;
#pragma unroll
    for (int i = 1; i < 64; i += 2) or_odd |= tok32[i];
    const int tstride = (or_odd == 0) ? 2 : 1;

    const int lr = tid >> 2;          // A-load row 0..63
    const int lc = (tid & 3) << 2;    // A-load k offset {0,4,8,12}
    const int kr = tid >> 4;          // B-load k row 0..15
    const int nc = (tid & 15) << 2;   // B-load n col {0..60}
    const int ty = tid >> 4, tx = tid & 15;

    float acc[8][8];
#pragma unroll
    for (int i = 0; i < 8; i++)
#pragma unroll
        for (int j = 0; j < 8; j++) acc[i][j] = 0.0f;

    for (int k0 = 0; k0 < H_; k0 += 16) {
#pragma unroll
        for (int r = 0; r < 2; r++) {
            int row = lr + r * 64;
            int token = tok32[(size_t)(bm + row) * tstride];
            float4 v = *(const float4*)(emb + (size_t)token * H_ + k0 + lc);
            As[lc + 0][row] = v.x; As[lc + 1][row] = v.y;
            As[lc + 2][row] = v.z; As[lc + 3][row] = v.w;
        }
        {
            const float* brow = Bg + (size_t)(k0 + kr) * H_ + bn;
            float4 w0 = *(const float4*)(brow + nc);
            float4 w1 = *(const float4*)(brow + nc + 64);
            *(float4*)&Bs[kr][nc] = w0;
            *(float4*)&Bs[kr][nc + 64] = w1;
        }
        __syncthreads();
#pragma unroll
        for (int k = 0; k < 16; k++) {
            float4 a0 = *(const float4*)&As[k][ty * 8];
            float4 a1 = *(const float4*)&As[k][ty * 8 + 4];
            float4 b0 = *(const float4*)&Bs[k][tx * 8];
            float4 b1 = *(const float4*)&Bs[k][tx * 8 + 4];
            float a[8] = {a0.x, a0.y, a0.z, a0.w, a1.x, a1.y, a1.z, a1.w};
            float b[8] = {b0.x, b0.y, b0.z, b0.w, b1.x, b1.y, b1.z, b1.w};
#pragma unroll
            for (int i = 0; i < 8; i++)
#pragma unroll
                for (int j = 0; j < 8; j++) acc[i][j] = fmaf(a[i], b[j], acc[i][j]);
        }
        __syncthreads();
    }
#pragma unroll
    for (int i = 0; i < 8; i++) {
        int m = bm + ty * 8 + i;
        size_t base = (size_t)m * (3 * H_) + (size_t)g * H_ + bn;
#pragma unroll
        for (int j = 0; j < 8; j++) {
            int n = tx * 8 + j;
            g_ax0[base + n] = acc[i][j] + bg[bn + n];
        }
    }
}

// ---------------- Kernel 2: persistent recurrence -------------------------
// Phases per step:
//  P1: r0,z0 from h0@U0[0..1] (+ precomputed ax0); raw dots h1@U1[0..1]
//  P2: h0_new = gate update with (r0*h0)@U0[2]
//  P3: ax1 = h0_new@Wx1 (+bx1); finish r1,z1; stash r1*h1, z1, ax1[2]
//  P4: h1_new with (r1*h1)@U1[2]; write tops[t]
__global__ __launch_bounds__(256) void gru_rec(const float* __restrict__ Wx,
                                               const float* __restrict__ bx,
                                               const float* __restrict__ U,
                                               const float* __restrict__ h0in,
                                               float* hf_out,
                                               int nblocks) {
    const int NT = nblocks * blockDim.x;
    const int gt = blockIdx.x * blockDim.x + threadIdx.x;

    // init hidden state from input h0 [L,B,H]
    for (int i = gt; i < 2 * B_ * H_; i += NT) g_h[i] = h0in[i];
    grid_barrier(nblocks);

    for (int t = 0; t < S_; t++) {
        // ---- P1 ----
        for (int idx = gt; idx < 2 * B_ * H_; idx += NT) {
            int half = idx >> 14;          // 0: layer0 rz, 1: layer1 rz raw dots
            int e = idx & (B_ * H_ - 1);
            int b = e >> 9;
            int o = e & (H_ - 1);
            const float* hrow = g_h + half * B_ * H_ + b * H_;
            const float* p0 = U + (size_t)(half * 3 + 0) * H_ * H_ + o;
            const float* p1 = U + (size_t)(half * 3 + 1) * H_ * H_ + o;
            float ar = 0.0f, az = 0.0f;
#pragma unroll 8
            for (int i = 0; i < H_; ++i) {
                float hv = hrow[i];
                ar = fmaf(hv, p0[0], ar);
                az = fmaf(hv, p1[0], az);
                p0 += H_; p1 += H_;
            }
            if (half == 0) {
                const float* axp = g_ax0 + (size_t)(t * B_ + b) * (3 * H_);
                float r = sigmoidf_(ar + axp[o]);
                float z = sigmoidf_(az + axp[H_ + o]);
                g_rh0[e] = r * hrow[o];
                g_z0[e] = z;
            } else {
                g_dr1[e] = ar;
                g_dz1[e] = az;
            }
        }
        grid_barrier(nblocks);

        // ---- P2 ----
        for (int e = gt; e < B_ * H_; e += NT) {
            int b = e >> 9;
            int o = e & (H_ - 1);
            const float* rh = g_rh0 + b * H_;
            const float* p2 = U + (size_t)2 * H_ * H_ + o;
            float acc = 0.0f;
#pragma unroll 8
            for (int i = 0; i < H_; ++i) { acc = fmaf(rh[i], p2[0], acc); p2 += H_; }
            float axh = g_ax0[(size_t)(t * B_ + b) * (3 * H_) + 2 * H_ + o];
            float hh = tanhf(axh + acc);
            float z = g_z0[e];
            float hold = g_h[e];
            g_h[e] = hold + z * (hh - hold);
        }
        grid_barrier(nblocks);

        // ---- P3 ----
        for (int e = gt; e < B_ * H_; e += NT) {
            int b = e >> 9;
            int o = e & (H_ - 1);
            const float* x = g_h + b * H_;  // h0_new
            const float* w0 = Wx + (size_t)(3 + 0) * H_ * H_ + o;
            const float* w1 = Wx + (size_t)(3 + 1) * H_ * H_ + o;
            const float* w2 = Wx + (size_t)(3 + 2) * H_ * H_ + o;
            float a0 = 0.0f, a1 = 0.0f, a2 = 0.0f;
#pragma unroll 4
            for (int i = 0; i < H_; ++i) {
                float xv = x[i];
                a0 = fmaf(xv, w0[0], a0);
                a1 = fmaf(xv, w1[0], a1);
                a2 = fmaf(xv, w2[0], a2);
                w0 += H_; w1 += H_; w2 += H_;
            }
            const float* bxl = bx + 3 * H_;
            float r = sigmoidf_(a0 + bxl[o] + g_dr1[e]);
            float z = sigmoidf_(a1 + bxl[H_ + o] + g_dz1[e]);
            float h1old = g_h[B_ * H_ + e];
            g_rh1[e] = r * h1old;
            g_z1v[e] = z;
            g_axh1[e] = a2 + bxl[2 * H_ + o];
        }
        grid_barrier(nblocks);

        // ---- P4 ----
        for (int e = gt; e < B_ * H_; e += NT) {
            int b = e >> 9;
            int o = e & (H_ - 1);
            const float* rh = g_rh1 + b * H_;
            const float* p2 = U + (size_t)(3 + 2) * H_ * H_ + o;
            float acc = 0.0f;
#pragma unroll 8
            for (int i = 0; i < H_; ++i) { acc = fmaf(rh[i], p2[0], acc); p2 += H_; }
            float hh = tanhf(g_axh1[e] + acc);
            float z = g_z1v[e];
            float hold = g_h[B_ * H_ + e];
            float hnew = hold + z * (hh - hold);
            g_h[B_ * H_ + e] = hnew;
            g_tops[(size_t)t * B_ * H_ + e] = hnew;
        }
        grid_barrier(nblocks);
    }

    // write h_final [L,B,H]
    if (hf_out) {
        for (int i = gt; i < 2 * B_ * H_; i += NT) hf_out[i] = g_h[i];
    }
}

// ---------------- Kernel 3: logits = tops @ Wy^T + by ---------------------
// A = g_tops [4096,512] row-major, B = Wy [10000,512] row-major (NT GEMM).
// grid: (ceil(10000/128)=79, 32), 256 threads.
__global__ __launch_bounds__(256) void logits_gemm(const float* __restrict__ Wy,
                                                   const float* __restrict__ by,
                                                   float* __restrict__ out) {
    __shared__ float As[16][132];
    __shared__ float Bs[16][132];

    const int tid = threadIdx.x;
    const int bm = blockIdx.y * 128;
    const int bn = blockIdx.x * 128;
    const int lr = tid >> 2;
    const int lc = (tid & 3) << 2;
    const int ty = tid >> 4, tx = tid & 15;

    float acc[8][8];
#pragma unroll
    for (int i = 0; i < 8; i++)
#pragma unroll
        for (int j = 0; j < 8; j++) acc[i][j] = 0.0f;

    for (int k0 = 0; k0 < H_; k0 += 16) {
#pragma unroll
        for (int r = 0; r < 2; r++) {
            int row = lr + r * 64;
            float4 v = *(const float4*)(g_tops + (size_t)(bm + row) * H_ + k0 + lc);
            As[lc + 0][row] = v.x; As[lc + 1][row] = v.y;
            As[lc + 2][row] = v.z; As[lc + 3][row] = v.w;
            int n = bn + row;
            float4 w = make_float4(0.f, 0.f, 0.f, 0.f);
            if (n < V_) w = *(const float4*)(Wy + (size_t)n * H_ + k0 + lc);
            Bs[lc + 0][row] = w.x; Bs[lc + 1][row] = w.y;
            Bs[lc + 2][row] = w.z; Bs[lc + 3][row] = w.w;
        }
        __syncthreads();
#pragma unroll
        for (int k = 0; k < 16; k++) {
            float4 a0 = *(const float4*)&As[k][ty * 8];
            float4 a1 = *(const float4*)&As[k][ty * 8 + 4];
            float4 b0 = *(const float4*)&Bs[k][tx * 8];
            float4 b1 = *(const float4*)&Bs[k][tx * 8 + 4];
            float a[8] = {a0.x, a0.y, a0.z, a0.w, a1.x, a1.y, a1.z, a1.w};
            float b[8] = {b0.x, b0.y, b0.z, b0.w, b1.x, b1.y, b1.z, b1.w};
#pragma unroll
            for (int i = 0; i < 8; i++)
#pragma unroll
                for (int j = 0; j < 8; j++) acc[i][j] = fmaf(a[i], b[j], acc[i][j]);
        }
        __syncthreads();
    }
#pragma unroll
    for (int i = 0; i < 8; i++) {
        int m = bm + ty * 8 + i;
#pragma unroll
        for (int j = 0; j < 8; j++) {
            int n = bn + tx * 8 + j;
            if (n < V_) out[(size_t)m * V_ + n] = acc[i][j] + by[n];
        }
    }
}

// ---------------- launch --------------------------------------------------
extern "C" void kernel_launch(void* const* d_in, const int* in_sizes, int n_in,
                              void* d_out, int out_size) {
    const int*   tok32 = (const int*)d_in[0];      // int32 or int64 (auto-detected on device)
    const float* h0    = (const float*)d_in[1];
    const float* emb   = (const float*)d_in[2];
    const float* Wx    = (const float*)d_in[3];
    const float* bx    = (const float*)d_in[4];
    const float* U     = (const float*)d_in[5];
    const float* Wy    = (const float*)d_in[6];
    const float* by    = (const float*)d_in[7];
    float* out = (float*)d_out;

    // 1) layer-0 input projections for all timesteps
    dim3 gx(H_ / 128, (S_ * B_) / 128, 3);
    x0_gemm<<<gx, 256>>>(tok32, emb, Wx, bx);

    // 2) persistent recurrence (grid = #SMs, residency-guaranteed)
    int dev = 0;
    cudaGetDevice(&dev);
    int sms = 0;
    cudaDeviceGetAttribute(&sms, cudaDevAttrMultiProcessorCount, dev);
    if (sms <= 0) sms = 148;
    if (sms > 1024) sms = 1024;

    float* hf = nullptr;
    long long need = (long long)S_ * B_ * V_ + (long long)L_ * B_ * H_;
    if ((long long)out_size >= need) hf = out + (size_t)S_ * B_ * V_;

    gru_rec<<<sms, 256>>>(Wx, bx, U, h0, hf, sms);

    // 3) logits projection
    dim3 gl((V_ + 127) / 128, (S_ * B_) / 128);
    logits_gemm<<<gl, 256>>>(Wy, by, out);
}

// round 11
// speedup vs baseline: 3.4935x; 3.4935x over previous
#include <cuda_runtime.h>
#include <cstdint>

#define S_ 128
#define B_ 32
#define H_ 512
#define V_ 10000
#define L_ 2

#define NB_ 128            // persistent blocks (1/SM, <= 148 SMs)
#define TPB_ 256
#define OC_ 4              // output columns owned per block (512/128)

// ---------------- device scratch (no allocations allowed) ----------------
__device__ float g_ax0[S_ * B_ * 3 * H_];          // layer-0 input projections [s][b][g][h]
__device__ float g_tops[S_ * B_ * H_];             // top-layer outputs per step
__device__ float g_h[2 * B_ * H_];                 // hidden states [layer][b][h]
__device__ float g_rh0[B_ * H_];
__device__ float g_z0[B_ * H_];
__device__ float g_dr1[B_ * H_];
__device__ float g_dz1[B_ * H_];
__device__ float g_rh1[B_ * H_];
__device__ float g_z1v[B_ * H_];
__device__ float g_axh1[B_ * H_];
__device__ unsigned g_barcnt = 0;
__device__ unsigned g_bargen = 0;

// ---------------- grid barrier (all blocks resident) ----------------------
__device__ __forceinline__ void grid_barrier() {
    __syncthreads();
    if (threadIdx.x == 0) {
        __threadfence();  // release (gpu scope -> CCTL.IVALL)
        volatile unsigned* vgen = &g_bargen;
        unsigned gen = *vgen;
        unsigned arrived = atomicAdd(&g_barcnt, 1u);
        if (arrived == (unsigned)(NB_ - 1)) {
            atomicExch(&g_barcnt, 0u);
            __threadfence();
            atomicAdd(&g_bargen, 1u);
        } else {
            while (*vgen == gen) { __nanosleep(32); }
        }
        __threadfence();  // acquire: drop stale L1 lines
    }
    __syncthreads();
}

__device__ __forceinline__ float sigmoidf_(float x) {
    return 1.0f / (1.0f + expf(-x));
}

// ---------------- Kernel 1: X0 = emb[tokens] @ Wx0[g] + bx0[g] ------------
__global__ __launch_bounds__(256) void x0_gemm(const int* __restrict__ tok32,
                                               const float* __restrict__ emb,
                                               const float* __restrict__ Wx,
                                               const float* __restrict__ bx) {
    const int g = blockIdx.z;
    const float* Bg = Wx + (size_t)g * H_ * H_;
    const float* bg = bx + g * H_;

    __shared__ float As[16][132];
    __shared__ float Bs[16][132];

    const int tid = threadIdx.x;
    const int bm = blockIdx.y * 128;
    const int bn = blockIdx.x * 128;

    int or_odd = 0;
#pragma unroll
    for (int i = 1; i < 64; i += 2) or_odd |= tok32[i];
    const int tstride = (or_odd == 0) ? 2 : 1;

    const int lr = tid >> 2;
    const int lc = (tid & 3) << 2;
    const int kr = tid >> 4;
    const int nc = (tid & 15) << 2;
    const int ty = tid >> 4, tx = tid & 15;

    float acc[8][8];
#pragma unroll
    for (int i = 0; i < 8; i++)
#pragma unroll
        for (int j = 0; j < 8; j++) acc[i][j] = 0.0f;

    for (int k0 = 0; k0 < H_; k0 += 16) {
#pragma unroll
        for (int r = 0; r < 2; r++) {
            int row = lr + r * 64;
            int token = tok32[(size_t)(bm + row) * tstride];
            float4 v = *(const float4*)(emb + (size_t)token * H_ + k0 + lc);
            As[lc + 0][row] = v.x; As[lc + 1][row] = v.y;
            As[lc + 2][row] = v.z; As[lc + 3][row] = v.w;
        }
        {
            const float* brow = Bg + (size_t)(k0 + kr) * H_ + bn;
            float4 w0 = *(const float4*)(brow + nc);
            float4 w1 = *(const float4*)(brow + nc + 64);
            *(float4*)&Bs[kr][nc] = w0;
            *(float4*)&Bs[kr][nc + 64] = w1;
        }
        __syncthreads();
#pragma unroll
        for (int k = 0; k < 16; k++) {
            float4 a0 = *(const float4*)&As[k][ty * 8];
            float4 a1 = *(const float4*)&As[k][ty * 8 + 4];
            float4 b0 = *(const float4*)&Bs[k][tx * 8];
            float4 b1 = *(const float4*)&Bs[k][tx * 8 + 4];
            float a[8] = {a0.x, a0.y, a0.z, a0.w, a1.x, a1.y, a1.z, a1.w};
            float b[8] = {b0.x, b0.y, b0.z, b0.w, b1.x, b1.y, b1.z, b1.w};
#pragma unroll
            for (int i = 0; i < 8; i++)
#pragma unroll
                for (int j = 0; j < 8; j++) acc[i][j] = fmaf(a[i], b[j], acc[i][j]);
        }
        __syncthreads();
    }
#pragma unroll
    for (int i = 0; i < 8; i++) {
        int m = bm + ty * 8 + i;
        size_t base = (size_t)m * (3 * H_) + (size_t)g * H_ + bn;
#pragma unroll
        for (int j = 0; j < 8; j++) {
            int n = tx * 8 + j;
            g_ax0[base + n] = acc[i][j] + bg[bn + n];
        }
    }
}

// ---------------- Kernel 2: persistent recurrence (SMEM-resident weights) -
// Each block owns columns [obase, obase+4) of all 9 recurrence matrices:
//   m 0..5 = U[l][g] (l*3+g), m 6..8 = Wx[1][g].
// SMEM (floats): wsm[9*512*4] | hsA[32*513] | hsB[32*513] | red[256*4]
#define WSM_FLT   (9 * 512 * 4)
#define HS_FLT    (32 * 513)
#define RED_FLT   (256 * 4)
#define SMEM_FLT  (WSM_FLT + 2 * HS_FLT + RED_FLT)
#define SMEM_BYTES (SMEM_FLT * 4)

// stage a [32][512] global vector into SMEM as hs[b*513 + i] (bank-conflict-free)
__device__ __forceinline__ void stage_vec(const float* __restrict__ src,
                                          float* __restrict__ hs, int tid) {
    int b = tid & 31, c = tid >> 5;               // 8 chunks of 64 i
    const float4* s = reinterpret_cast<const float4*>(src + b * 512 + c * 64);
    float* d = hs + b * 513 + c * 64;
#pragma unroll
    for (int k = 0; k < 16; k++) {
        float4 v = s[k];
        d[k * 4 + 0] = v.x; d[k * 4 + 1] = v.y;
        d[k * 4 + 2] = v.z; d[k * 4 + 3] = v.w;
    }
}

// 4-column dot: acc[oc] += sum_i w[i][oc] * h[i] over i in [i0, i0+n)
__device__ __forceinline__ void dot4(const float4* __restrict__ wp,
                                     const float* __restrict__ hr,
                                     int i0, int n, float a[4]) {
#pragma unroll 8
    for (int i = i0; i < i0 + n; ++i) {
        float4 w = wp[i];
        float h = hr[i];
        a[0] = fmaf(w.x, h, a[0]);
        a[1] = fmaf(w.y, h, a[1]);
        a[2] = fmaf(w.z, h, a[2]);
        a[3] = fmaf(w.w, h, a[3]);
    }
}

__global__ __launch_bounds__(TPB_) void gru_rec(const float* __restrict__ Wx,
                                                const float* __restrict__ bx,
                                                const float* __restrict__ U,
                                                const float* __restrict__ h0in,
                                                float* hf_out) {
    extern __shared__ float smem[];
    float* wsm = smem;                       // [9][512][4]
    float* hsA = smem + WSM_FLT;             // [32][513]
    float* hsB = hsA + HS_FLT;
    float* red = hsB + HS_FLT;               // [256][4]
    float4* redq = reinterpret_cast<float4*>(red);

    const int tid = threadIdx.x;
    const int obase = blockIdx.x * OC_;

    // ---- one-time: load this block's weight column slices into SMEM ----
    for (int idx = tid; idx < 9 * 512; idx += TPB_) {
        int m = idx >> 9, i = idx & 511;
        const float* src = (m < 6)
            ? (U  + ((size_t)m * 512 + i) * 512 + obase)
            : (Wx + ((size_t)(3 + (m - 6)) * 512 + i) * 512 + obase);
        *reinterpret_cast<float4*>(&wsm[(size_t)idx * 4]) =
            *reinterpret_cast<const float4*>(src);
    }

    // init hidden state in global
    {
        const int NT = NB_ * TPB_;
        const int gt = blockIdx.x * TPB_ + tid;
        for (int i = gt; i < 2 * B_ * H_; i += NT) g_h[i] = h0in[i];
    }
    grid_barrier();

    const int b = tid & 31;

    for (int t = 0; t < S_; t++) {
        // ================= P1: r0,z0 + raw layer-1 r/z dots ================
        stage_vec(g_h, hsA, tid);                 // h0
        stage_vec(g_h + B_ * H_, hsB, tid);       // h1
        __syncthreads();
        {
            const int gu = (tid >> 5) & 3;        // 0:U00 1:U01 2:U10 3:U11
            const int ks = tid >> 7;              // 0/1
            const int m = (gu < 2) ? gu : (gu + 1);   // {0,1,3,4}
            const float* hr = ((gu < 2) ? hsA : hsB) + b * 513;
            const float4* wp = reinterpret_cast<const float4*>(wsm + (size_t)m * 2048);
            float a[4] = {0.f, 0.f, 0.f, 0.f};
            dot4(wp, hr, ks * 256, 256, a);
            redq[tid] = make_float4(a[0], a[1], a[2], a[3]);
        }
        __syncthreads();
        if (tid < 128) {
            const int gu = tid >> 5;
            float4 x = redq[tid], y = redq[tid + 128];
            float d[4] = {x.x + y.x, x.y + y.y, x.z + y.z, x.w + y.w};
            if (gu == 0) {
                const float* axp = g_ax0 + ((size_t)(t * B_ + b) * 3 + 0) * H_ + obase;
#pragma unroll
                for (int oc = 0; oc < 4; oc++) {
                    float r = sigmoidf_(d[oc] + axp[oc]);
                    g_rh0[b * H_ + obase + oc] = r * hsA[b * 513 + obase + oc];
                }
            } else if (gu == 1) {
                const float* axp = g_ax0 + ((size_t)(t * B_ + b) * 3 + 1) * H_ + obase;
#pragma unroll
                for (int oc = 0; oc < 4; oc++)
                    g_z0[b * H_ + obase + oc] = sigmoidf_(d[oc] + axp[oc]);
            } else if (gu == 2) {
#pragma unroll
                for (int oc = 0; oc < 4; oc++) g_dr1[b * H_ + obase + oc] = d[oc];
            } else {
#pragma unroll
                for (int oc = 0; oc < 4; oc++) g_dz1[b * H_ + obase + oc] = d[oc];
            }
        }
        grid_barrier();

        // ================= P2: h0_new ======================================
        stage_vec(g_rh0, hsA, tid);
        __syncthreads();
        {
            const int ks = tid >> 5;              // 8 chunks of 64
            const float4* wp = reinterpret_cast<const float4*>(wsm + (size_t)2 * 2048);
            float a[4] = {0.f, 0.f, 0.f, 0.f};
            dot4(wp, hsA + b * 513, ks * 64, 64, a);
            redq[tid] = make_float4(a[0], a[1], a[2], a[3]);
        }
        __syncthreads();
        if (tid < 32) {
            float d[4] = {0.f, 0.f, 0.f, 0.f};
#pragma unroll
            for (int j = 0; j < 8; j++) {
                float4 x = redq[tid + 32 * j];
                d[0] += x.x; d[1] += x.y; d[2] += x.z; d[3] += x.w;
            }
            const float* axp = g_ax0 + ((size_t)(t * B_ + b) * 3 + 2) * H_ + obase;
#pragma unroll
            for (int oc = 0; oc < 4; oc++) {
                int e = b * H_ + obase + oc;
                float hh = tanhf(axp[oc] + d[oc]);
                float z = g_z0[e];
                float hold = g_h[e];
                g_h[e] = hold + z * (hh - hold);
            }
        }
        grid_barrier();

        // ================= P3: ax1 + finish r1,z1 ==========================
        stage_vec(g_h, hsA, tid);                 // h0_new
        __syncthreads();
        if (tid < 192) {
            const int q = tid >> 5;               // 0..5
            const int g = q % 3, ks = q / 3;
            const float4* wp = reinterpret_cast<const float4*>(wsm + (size_t)(6 + g) * 2048);
            float a[4] = {0.f, 0.f, 0.f, 0.f};
            dot4(wp, hsA + b * 513, ks * 256, 256, a);
            redq[tid] = make_float4(a[0], a[1], a[2], a[3]);
        }
        __syncthreads();
        if (tid < 96) {
            const int g = tid >> 5;
            float4 x = redq[tid], y = redq[tid + 96];
            float d[4] = {x.x + y.x, x.y + y.y, x.z + y.z, x.w + y.w};
            const float* bxl = bx + (size_t)(3 + g) * H_ + obase;
            if (g == 0) {
#pragma unroll
                for (int oc = 0; oc < 4; oc++) {
                    int e = b * H_ + obase + oc;
                    float r = sigmoidf_(d[oc] + bxl[oc] + g_dr1[e]);
                    g_rh1[e] = r * g_h[B_ * H_ + e];
                }
            } else if (g == 1) {
#pragma unroll
                for (int oc = 0; oc < 4; oc++) {
                    int e = b * H_ + obase + oc;
                    g_z1v[e] = sigmoidf_(d[oc] + bxl[oc] + g_dz1[e]);
                }
            } else {
#pragma unroll
                for (int oc = 0; oc < 4; oc++) {
                    int e = b * H_ + obase + oc;
                    g_axh1[e] = d[oc] + bxl[oc];
                }
            }
        }
        grid_barrier();

        // ================= P4: h1_new + tops ===============================
        stage_vec(g_rh1, hsA, tid);
        __syncthreads();
        {
            const int ks = tid >> 5;
            const float4* wp = reinterpret_cast<const float4*>(wsm + (size_t)5 * 2048);
            float a[4] = {0.f, 0.f, 0.f, 0.f};
            dot4(wp, hsA + b * 513, ks * 64, 64, a);
            redq[tid] = make_float4(a[0], a[1], a[2], a[3]);
        }
        __syncthreads();
        if (tid < 32) {
            float d[4] = {0.f, 0.f, 0.f, 0.f};
#pragma unroll
            for (int j = 0; j < 8; j++) {
                float4 x = redq[tid + 32 * j];
                d[0] += x.x; d[1] += x.y; d[2] += x.z; d[3] += x.w;
            }
#pragma unroll
            for (int oc = 0; oc < 4; oc++) {
                int e = b * H_ + obase + oc;
                float hh = tanhf(g_axh1[e] + d[oc]);
                float z = g_z1v[e];
                float hold = g_h[B_ * H_ + e];
                float hnew = hold + z * (hh - hold);
                g_h[B_ * H_ + e] = hnew;
                g_tops[(size_t)t * B_ * H_ + e] = hnew;
            }
        }
        grid_barrier();
    }

    if (hf_out) {
        const int NT = NB_ * TPB_;
        const int gt = blockIdx.x * TPB_ + tid;
        for (int i = gt; i < 2 * B_ * H_; i += NT) hf_out[i] = g_h[i];
    }
}

// ---------------- Kernel 3: logits = tops @ Wy^T + by ---------------------
__global__ __launch_bounds__(256) void logits_gemm(const float* __restrict__ Wy,
                                                   const float* __restrict__ by,
                                                   float* __restrict__ out) {
    __shared__ float As[16][132];
    __shared__ float Bs[16][132];

    const int tid = threadIdx.x;
    const int bm = blockIdx.y * 128;
    const int bn = blockIdx.x * 128;
    const int lr = tid >> 2;
    const int lc = (tid & 3) << 2;
    const int ty = tid >> 4, tx = tid & 15;

    float acc[8][8];
#pragma unroll
    for (int i = 0; i < 8; i++)
#pragma unroll
        for (int j = 0; j < 8; j++) acc[i][j] = 0.0f;

    for (int k0 = 0; k0 < H_; k0 += 16) {
#pragma unroll
        for (int r = 0; r < 2; r++) {
            int row = lr + r * 64;
            float4 v = *(const float4*)(g_tops + (size_t)(bm + row) * H_ + k0 + lc);
            As[lc + 0][row] = v.x; As[lc + 1][row] = v.y;
            As[lc + 2][row] = v.z; As[lc + 3][row] = v.w;
            int n = bn + row;
            float4 w = make_float4(0.f, 0.f, 0.f, 0.f);
            if (n < V_) w = *(const float4*)(Wy + (size_t)n * H_ + k0 + lc);
            Bs[lc + 0][row] = w.x; Bs[lc + 1][row] = w.y;
            Bs[lc + 2][row] = w.z; Bs[lc + 3][row] = w.w;
        }
        __syncthreads();
#pragma unroll
        for (int k = 0; k < 16; k++) {
            float4 a0 = *(const float4*)&As[k][ty * 8];
            float4 a1 = *(const float4*)&As[k][ty * 8 + 4];
            float4 b0 = *(const float4*)&Bs[k][tx * 8];
            float4 b1 = *(const float4*)&Bs[k][tx * 8 + 4];
            float a[8] = {a0.x, a0.y, a0.z, a0.w, a1.x, a1.y, a1.z, a1.w};
            float b[8] = {b0.x, b0.y, b0.z, b0.w, b1.x, b1.y, b1.z, b1.w};
#pragma unroll
            for (int i = 0; i < 8; i++)
#pragma unroll
                for (int j = 0; j < 8; j++) acc[i][j] = fmaf(a[i], b[j], acc[i][j]);
        }
        __syncthreads();
    }
#pragma unroll
    for (int i = 0; i < 8; i++) {
        int m = bm + ty * 8 + i;
#pragma unroll
        for (int j = 0; j < 8; j++) {
            int n = bn + tx * 8 + j;
            if (n < V_) out[(size_t)m * V_ + n] = acc[i][j] + by[n];
        }
    }
}

// ---------------- launch --------------------------------------------------
extern "C" void kernel_launch(void* const* d_in, const int* in_sizes, int n_in,
                              void* d_out, int out_size) {
    const int*   tok32 = (const int*)d_in[0];
    const float* h0    = (const float*)d_in[1];
    const float* emb   = (const float*)d_in[2];
    const float* Wx    = (const float*)d_in[3];
    const float* bx    = (const float*)d_in[4];
    const float* U     = (const float*)d_in[5];
    const float* Wy    = (const float*)d_in[6];
    const float* by    = (const float*)d_in[7];
    float* out = (float*)d_out;

    // 1) layer-0 input projections for all timesteps
    dim3 gx(H_ / 128, (S_ * B_) / 128, 3);
    x0_gemm<<<gx, 256>>>(tok32, emb, Wx, bx);

    // 2) persistent recurrence with SMEM-resident weights
    static int smem_set = 0;
    if (!smem_set) {
        cudaFuncSetAttribute(gru_rec, cudaFuncAttributeMaxDynamicSharedMemorySize,
                             SMEM_BYTES);
        smem_set = 1;
    }
    float* hf = nullptr;
    long long need = (long long)S_ * B_ * V_ + (long long)L_ * B_ * H_;
    if ((long long)out_size >= need) hf = out + (size_t)S_ * B_ * V_;

    gru_rec<<<NB_, TPB_, SMEM_BYTES>>>(Wx, bx, U, h0, hf);

    // 3) logits projection
    dim3 gl((V_ + 127) / 128, (S_ * B_) / 128);
    logits_gemm<<<gl, 256>>>(Wy, by, out);
}

// round 14
// speedup vs baseline: 5.6386x; 1.6140x over previous
#include <cuda_runtime.h>
#include <cstdint>

#define S_ 128
#define B_ 32
#define H_ 512
#define V_ 10000
#define L_ 2

#define NB_ 128            // persistent blocks (1/SM)
#define TPB_ 256

// ---------------- device scratch (no allocations allowed) ----------------
__device__ __align__(16) float g_ax0[S_ * B_ * 3 * H_];   // [s][b][3][512]
__device__ __align__(16) float g_tops[S_ * B_ * H_];      // [t*32+b][512]
__device__ __align__(16) float g_h0T[H_ * B_];            // transposed [o][b]
__device__ __align__(16) float g_h1T[H_ * B_];
__device__ __align__(16) float g_rh0T[H_ * B_];
__device__ __align__(16) float g_rh1T[H_ * B_];
__device__ unsigned g_barcnt = 0;
__device__ unsigned g_bargen = 0;

// ---------------- packed f32x2 helpers ------------------------------------
__device__ __forceinline__ unsigned long long pack2(float lo, float hi) {
    unsigned long long r;
    asm("mov.b64 %0, {%1, %2};" : "=l"(r) : "f"(lo), "f"(hi));
    return r;
}
__device__ __forceinline__ void unpack2(unsigned long long v, float& lo, float& hi) {
    asm("mov.b64 {%0, %1}, %2;" : "=f"(lo), "=f"(hi) : "l"(v));
}
__device__ __forceinline__ void ffma2(unsigned long long& d,
                                      unsigned long long a, unsigned long long b) {
    asm("fma.rn.f32x2 %0, %1, %2, %0;" : "+l"(d) : "l"(a), "l"(b));
}

// ---------------- grid barrier (self-resetting; replay-safe) --------------
// State returns to {count=0} after every barrier; gen is read fresh each
// time, so the scheme does not depend on launch count (graph-replay safe).
__device__ __forceinline__ void gbar() {
    __syncthreads();
    if (threadIdx.x == 0) {
        __threadfence();  // release my CTA's prior global writes
        volatile unsigned* vgen = &g_bargen;
        unsigned gen = *vgen;
        unsigned prev = atomicAdd(&g_barcnt, 1u);
        if (prev == (unsigned)(NB_ - 1)) {
            atomicExch(&g_barcnt, 0u);   // reset BEFORE release
            __threadfence();
            atomicAdd(&g_bargen, 1u);    // release waiters
        } else {
            while (*vgen == gen) { __nanosleep(20); }
        }
        __threadfence();  // acquire: invalidate stale L1 lines (CCTL.IVALL)
    }
    __syncthreads();
}

__device__ __forceinline__ float sigmoidf_(float x) {
    return 1.0f / (1.0f + expf(-x));
}

// ---------------- Kernel 1: X0 = emb[tokens] @ Wx0[g] + bx0[g] ------------
__global__ __launch_bounds__(256) void x0_gemm(const int* __restrict__ tok32,
                                               const float* __restrict__ emb,
                                               const float* __restrict__ Wx,
                                               const float* __restrict__ bx) {
    const int g = blockIdx.z;
    const float* Bg = Wx + (size_t)g * H_ * H_;
    const float* bg = bx + g * H_;

    __shared__ float As[16][132];
    __shared__ float Bs[16][132];

    const int tid = threadIdx.x;
    const int bm = blockIdx.y * 128;
    const int bn = blockIdx.x * 128;

    int or_odd = 0;
#pragma unroll
    for (int i = 1; i < 64; i += 2) or_odd |= tok32[i];
    const int tstride = (or_odd == 0) ? 2 : 1;

    const int lr = tid >> 2;
    const int lc = (tid & 3) << 2;
    const int kr = tid >> 4;
    const int nc = (tid & 15) << 2;
    const int ty = tid >> 4, tx = tid & 15;

    unsigned long long acc2[8][4];
#pragma unroll
    for (int i = 0; i < 8; i++)
#pragma unroll
        for (int j = 0; j < 4; j++) acc2[i][j] = 0ull;

    for (int k0 = 0; k0 < H_; k0 += 16) {
#pragma unroll
        for (int r = 0; r < 2; r++) {
            int row = lr + r * 64;
            int token = tok32[(size_t)(bm + row) * tstride];
            float4 v = *(const float4*)(emb + (size_t)token * H_ + k0 + lc);
            As[lc + 0][row] = v.x; As[lc + 1][row] = v.y;
            As[lc + 2][row] = v.z; As[lc + 3][row] = v.w;
        }
        {
            const float* brow = Bg + (size_t)(k0 + kr) * H_ + bn;
            float4 w0 = *(const float4*)(brow + nc);
            float4 w1 = *(const float4*)(brow + nc + 64);
            *(float4*)&Bs[kr][nc] = w0;
            *(float4*)&Bs[kr][nc + 64] = w1;
        }
        __syncthreads();
#pragma unroll
        for (int k = 0; k < 16; k++) {
            float4 a0 = *(const float4*)&As[k][ty * 8];
            float4 a1 = *(const float4*)&As[k][ty * 8 + 4];
            ulonglong2 b01 = *(const ulonglong2*)&Bs[k][tx * 8];
            ulonglong2 b23 = *(const ulonglong2*)&Bs[k][tx * 8 + 4];
            unsigned long long bp[4] = {b01.x, b01.y, b23.x, b23.y};
            float a[8] = {a0.x, a0.y, a0.z, a0.w, a1.x, a1.y, a1.z, a1.w};
#pragma unroll
            for (int i = 0; i < 8; i++) {
                unsigned long long ai = pack2(a[i], a[i]);
#pragma unroll
                for (int j = 0; j < 4; j++) ffma2(acc2[i][j], ai, bp[j]);
            }
        }
        __syncthreads();
    }
#pragma unroll
    for (int i = 0; i < 8; i++) {
        int m = bm + ty * 8 + i;
        size_t base = (size_t)m * (3 * H_) + (size_t)g * H_ + bn;
#pragma unroll
        for (int j = 0; j < 4; j++) {
            float c0, c1; unpack2(acc2[i][j], c0, c1);
            int n = tx * 8 + j * 2;
            g_ax0[base + n]     = c0 + bg[bn + n];
            g_ax0[base + n + 1] = c1 + bg[bn + n + 1];
        }
    }
}

// ---------------- Kernel 2: persistent pipelined recurrence ---------------
// Superstep k (0..128): Phase A computes r0/z0 for h0(k) [k<128], and
// r1/z1 + ax1 for h1(k-1) [k>=1]; Phase B applies both h updates.
// Per block: owns 4 output columns of all 9 matrices (SMEM-resident).
#define OFF_WSM 0
#define OFF_SH0 (9 * 512 * 4)
#define OFF_SH1 (OFF_SH0 + 512 * 32)
#define OFF_RED (OFF_SH1 + 512 * 32)
#define OFF_Z0  (OFF_RED + 16 * 32 * 4)
#define OFF_Z1  (OFF_Z0 + 128)
#define OFF_AXH (OFF_Z1 + 128)
#define OFF_BX1 (OFF_AXH + 128)
#define SMEM_FLT (OFF_BX1 + 16)
#define SMEM_BYTES (SMEM_FLT * 4)

__global__ __launch_bounds__(TPB_) void gru_rec(const float* __restrict__ Wx,
                                                const float* __restrict__ bx,
                                                const float* __restrict__ U,
                                                const float* __restrict__ h0in,
                                                float* hf_out) {
    extern __shared__ float smem[];
    float* wsm   = smem + OFF_WSM;
    float* sh0   = smem + OFF_SH0;
    float* sh1   = smem + OFF_SH1;
    float* s_red = smem + OFF_RED;     // [16][32][4]
    float* s_z0  = smem + OFF_Z0;      // [4][32]
    float* s_z1  = smem + OFF_Z1;
    float* s_axh = smem + OFF_AXH;
    float* s_bx1 = smem + OFF_BX1;     // [3][4]

    const int tid  = threadIdx.x;
    const int lane = tid & 31;
    const int wid  = tid >> 5;
    const int obase = blockIdx.x * 4;

    // one-time weight slice load: m 0..5 = U[l*3+g], 6..8 = Wx[1][g]
    for (int idx = tid; idx < 9 * 512; idx += TPB_) {
        int m = idx >> 9, i = idx & 511;
        const float* src = (m < 6)
            ? (U  + ((size_t)m * 512 + i) * 512 + obase)
            : (Wx + ((size_t)(3 + (m - 6)) * 512 + i) * 512 + obase);
        *(float4*)&wsm[(size_t)idx * 4] = *(const float4*)src;
    }
    if (tid < 12) s_bx1[tid] = bx[(size_t)(3 + (tid >> 2)) * 512 + obase + (tid & 3)];

    // init transposed hidden states
    {
        const int NT = NB_ * TPB_;
        for (int i = blockIdx.x * TPB_ + tid; i < 2 * B_ * H_; i += NT) {
            int l = i >> 14, rem = i & 16383, b = rem >> 9, o = rem & 511;
            (l ? g_h1T : g_h0T)[o * 32 + b] = h0in[i];
        }
    }
    gbar();

    for (int k = 0; k <= S_; k++) {
        // ================= Phase A =================
        {   // stage h0T, h1T (coalesced)
            const float4* s0 = (const float4*)g_h0T;
            const float4* s1 = (const float4*)g_h1T;
            float4* d0 = (float4*)sh0; float4* d1 = (float4*)sh1;
            for (int i = tid; i < 4096; i += TPB_) { d0[i] = s0[i]; d1[i] = s1[i]; }
        }
        __syncthreads();
        {   // 7 dots (d: 0=U00 1=U01 2=U10 3=U11 4..6=Wx1 g), flattened
            // iter space 7*512 = 3584; warp w covers [w*448, w*448+448), <=2 segments
            int cur = wid * 448;
            const int endall = cur + 448;
            int d = cur >> 9;
#pragma unroll
            for (int seg = 0; seg < 2; seg++) {
                unsigned long long a01 = 0ull, a23 = 0ull;
                if (cur < endall && d < 7) {
                    int stop = min(endall, (d + 1) << 9);
                    int m = (d < 2) ? d : ((d < 4) ? d + 1 : d + 2);
                    const float* hsv = (d == 2 || d == 3) ? sh1 : sh0;
                    const ulonglong2* wp = (const ulonglong2*)(wsm + (size_t)m * 2048);
#pragma unroll 8
                    for (int i = cur; i < stop; ++i) {
                        int il = i & 511;
                        ulonglong2 w = wp[il];
                        float hv = hsv[il * 32 + lane];
                        unsigned long long h2 = pack2(hv, hv);
                        ffma2(a01, w.x, h2);
                        ffma2(a23, w.y, h2);
                    }
                    cur = stop; d++;
                }
                float c0, c1, c2, c3;
                unpack2(a01, c0, c1); unpack2(a23, c2, c3);
                *(float4*)&s_red[((wid * 2 + seg) * 32 + lane) * 4] =
                    make_float4(c0, c1, c2, c3);
            }
        }
        __syncthreads();
        if (tid < 128) {   // combine: thread = (b=lane, oc=wid)
            const int b = lane, oc = wid;
            const int segd[16] = {0,1, 0,1, 1,2, 2,3, 3,4, 4,5, 5,6, 6,7};
            float dsum[7] = {0.f, 0.f, 0.f, 0.f, 0.f, 0.f, 0.f};
#pragma unroll
            for (int s = 0; s < 16; s++) {
                if (segd[s] < 7) dsum[segd[s]] += s_red[(s * 32 + b) * 4 + oc];
            }
            const int col = obase + oc;
            if (k < S_) {
                const float* axp = g_ax0 + ((size_t)(k * 32 + b) * 3) * 512 + col;
                float r0 = sigmoidf_(dsum[0] + axp[0]);
                float z0 = sigmoidf_(dsum[1] + axp[512]);
                s_z0[oc * 32 + b] = z0;
                g_rh0T[col * 32 + b] = r0 * sh0[col * 32 + b];
            }
            if (k >= 1) {
                float r1 = sigmoidf_(dsum[2] + dsum[4] + s_bx1[oc]);
                float z1 = sigmoidf_(dsum[3] + dsum[5] + s_bx1[4 + oc]);
                s_z1[oc * 32 + b] = z1;
                s_axh[oc * 32 + b] = dsum[6] + s_bx1[8 + oc];
                g_rh1T[col * 32 + b] = r1 * sh1[col * 32 + b];
            }
        }
        gbar();

        // ================= Phase B =================
        {   // stage rh0T, rh1T
            const float4* s0 = (const float4*)g_rh0T;
            const float4* s1 = (const float4*)g_rh1T;
            float4* d0 = (float4*)sh0; float4* d1 = (float4*)sh1;
            for (int i = tid; i < 4096; i += TPB_) { d0[i] = s0[i]; d1[i] = s1[i]; }
        }
        __syncthreads();
        {   // warps 0-3: U02·rh0 (K/4 each); warps 4-7: U12·rh1
            const int m = (wid < 4) ? 2 : 5;
            const float* hsv = (wid < 4) ? sh0 : sh1;
            const int i0 = (wid & 3) * 128;
            const ulonglong2* wp = (const ulonglong2*)(wsm + (size_t)m * 2048);
            unsigned long long a01 = 0ull, a23 = 0ull;
#pragma unroll 8
            for (int i = i0; i < i0 + 128; ++i) {
                ulonglong2 w = wp[i];
                float hv = hsv[i * 32 + lane];
                unsigned long long h2 = pack2(hv, hv);
                ffma2(a01, w.x, h2);
                ffma2(a23, w.y, h2);
            }
            float c0, c1, c2, c3;
            unpack2(a01, c0, c1); unpack2(a23, c2, c3);
            *(float4*)&s_red[(wid * 32 + lane) * 4] = make_float4(c0, c1, c2, c3);
        }
        __syncthreads();
        if (tid < 128) {
            const int b = lane, oc = wid;
            const int col = obase + oc;
            if (k < S_) {
                float dsum = s_red[(0 * 32 + b) * 4 + oc] + s_red[(1 * 32 + b) * 4 + oc]
                           + s_red[(2 * 32 + b) * 4 + oc] + s_red[(3 * 32 + b) * 4 + oc];
                float axh0 = g_ax0[((size_t)(k * 32 + b) * 3 + 2) * 512 + col];
                float hh = tanhf(axh0 + dsum);
                float z = s_z0[oc * 32 + b];
                float hold = g_h0T[col * 32 + b];
                g_h0T[col * 32 + b] = hold + z * (hh - hold);
            }
            if (k >= 1) {
                float dsum = s_red[(4 * 32 + b) * 4 + oc] + s_red[(5 * 32 + b) * 4 + oc]
                           + s_red[(6 * 32 + b) * 4 + oc] + s_red[(7 * 32 + b) * 4 + oc];
                float hh = tanhf(s_axh[oc * 32 + b] + dsum);
                float z = s_z1[oc * 32 + b];
                float hold = g_h1T[col * 32 + b];
                float hnew = hold + z * (hh - hold);
                g_h1T[col * 32 + b] = hnew;
                g_tops[((size_t)(k - 1) * 32 + b) * 512 + col] = hnew;
            }
        }
        gbar();
    }

    if (hf_out) {   // h_final [L][B][H] from transposed state
        const int NT = NB_ * TPB_;
        for (int i = blockIdx.x * TPB_ + tid; i < 2 * B_ * H_; i += NT) {
            int l = i >> 14, rem = i & 16383, b = rem >> 9, o = rem & 511;
            hf_out[i] = (l ? g_h1T : g_h0T)[o * 32 + b];
        }
    }
}

// ---------------- Kernel 3: logits = tops @ Wy^T + by ---------------------
__global__ __launch_bounds__(256) void logits_gemm(const float* __restrict__ Wy,
                                                   const float* __restrict__ by,
                                                   float* __restrict__ out) {
    __shared__ float As[16][132];
    __shared__ float Bs[16][132];

    const int tid = threadIdx.x;
    const int bm = blockIdx.y * 128;
    const int bn = blockIdx.x * 128;
    const int lr = tid >> 2;
    const int lc = (tid & 3) << 2;
    const int ty = tid >> 4, tx = tid & 15;

    unsigned long long acc2[8][4];
#pragma unroll
    for (int i = 0; i < 8; i++)
#pragma unroll
        for (int j = 0; j < 4; j++) acc2[i][j] = 0ull;

    for (int k0 = 0; k0 < H_; k0 += 16) {
#pragma unroll
        for (int r = 0; r < 2; r++) {
            int row = lr + r * 64;
            float4 v = *(const float4*)(g_tops + (size_t)(bm + row) * H_ + k0 + lc);
            As[lc + 0][row] = v.x; As[lc + 1][row] = v.y;
            As[lc + 2][row] = v.z; As[lc + 3][row] = v.w;
            int n = bn + row;
            float4 w = make_float4(0.f, 0.f, 0.f, 0.f);
            if (n < V_) w = *(const float4*)(Wy + (size_t)n * H_ + k0 + lc);
            Bs[lc + 0][row] = w.x; Bs[lc + 1][row] = w.y;
            Bs[lc + 2][row] = w.z; Bs[lc + 3][row] = w.w;
        }
        __syncthreads();
#pragma unroll
        for (int k = 0; k < 16; k++) {
            float4 a0 = *(const float4*)&As[k][ty * 8];
            float4 a1 = *(const float4*)&As[k][ty * 8 + 4];
            ulonglong2 b01 = *(const ulonglong2*)&Bs[k][tx * 8];
            ulonglong2 b23 = *(const ulonglong2*)&Bs[k][tx * 8 + 4];
            unsigned long long bp[4] = {b01.x, b01.y, b23.x, b23.y};
            float a[8] = {a0.x, a0.y, a0.z, a0.w, a1.x, a1.y, a1.z, a1.w};
#pragma unroll
            for (int i = 0; i < 8; i++) {
                unsigned long long ai = pack2(a[i], a[i]);
#pragma unroll
                for (int j = 0; j < 4; j++) ffma2(acc2[i][j], ai, bp[j]);
            }
        }
        __syncthreads();
    }
#pragma unroll
    for (int i = 0; i < 8; i++) {
        int m = bm + ty * 8 + i;
#pragma unroll
        for (int j = 0; j < 4; j++) {
            float c0, c1; unpack2(acc2[i][j], c0, c1);
            int n = bn + tx * 8 + j * 2;
            if (n < V_)     out[(size_t)m * V_ + n]     = c0 + by[n];
            if (n + 1 < V_) out[(size_t)m * V_ + n + 1] = c1 + by[n + 1];
        }
    }
}

// ---------------- launch --------------------------------------------------
extern "C" void kernel_launch(void* const* d_in, const int* in_sizes, int n_in,
                              void* d_out, int out_size) {
    const int*   tok32 = (const int*)d_in[0];
    const float* h0    = (const float*)d_in[1];
    const float* emb   = (const float*)d_in[2];
    const float* Wx    = (const float*)d_in[3];
    const float* bx    = (const float*)d_in[4];
    const float* U     = (const float*)d_in[5];
    const float* Wy    = (const float*)d_in[6];
    const float* by    = (const float*)d_in[7];
    float* out = (float*)d_out;

    // 1) layer-0 input projections for all timesteps
    dim3 gx(H_ / 128, (S_ * B_) / 128, 3);
    x0_gemm<<<gx, 256>>>(tok32, emb, Wx, bx);

    // 2) persistent pipelined recurrence
    static int smem_set = 0;
    if (!smem_set) {
        cudaFuncSetAttribute(gru_rec, cudaFuncAttributeMaxDynamicSharedMemorySize,
                             SMEM_BYTES);
        smem_set = 1;
    }
    float* hf = nullptr;
    long long need = (long long)S_ * B_ * V_ + (long long)L_ * B_ * H_;
    if ((long long)out_size >= need) hf = out + (size_t)S_ * B_ * V_;

    gru_rec<<<NB_, TPB_, SMEM_BYTES>>>(Wx, bx, U, h0, hf);

    // 3) logits projection
    dim3 gl((V_ + 127) / 128, (S_ * B_) / 128);
    logits_gemm<<<gl, 256>>>(Wy, by, out);
}